// round 1
// baseline (speedup 1.0000x reference)
#include <cuda_runtime.h>
#include <stdint.h>

// Problem constants (from reference)
//   IN:  (4, 64, 224, 224) fp32
//   OUT: (4, 576, 223*223) fp32  -- note nh=K+D=4 => out spatial 223, not 224
#define B_   4
#define C_   64
#define H_   224
#define W_   224
#define K_   3
#define OH_  223
#define OW_  223
#define OSP  (OH_ * OW_)            // 49729
#define OUT_ELEMS 114575616u        // 4*576*49729
#define N4   (OUT_ELEMS / 4u)       // 28643904

__global__ void __launch_bounds__(256) unfold_kernel(const float* __restrict__ x,
                                                     float* __restrict__ out) {
    unsigned i4 = blockIdx.x * 256u + threadIdx.x;
    if (i4 >= N4) return;
    unsigned base = i4 * 4u;

    float4 v;
    float* vp = &v.x;

#pragma unroll
    for (int t = 0; t < 4; ++t) {
        unsigned idx = base + (unsigned)t;
        // decompose: idx = ck * OSP + oh*OW + ow ; ck = ((b*C + c)*3 + ki)*3 + kj
        unsigned ck      = idx / OSP;       // constant divisor -> umulhi
        unsigned spatial = idx - ck * OSP;
        unsigned oh = spatial / OW_;
        unsigned ow = spatial - oh * OW_;
        unsigned kj  = ck % 3u;
        unsigned ck3 = ck / 3u;
        unsigned ki  = ck3 % 3u;
        unsigned bc  = ck3 / 3u;            // b*C + c

        int ih = (int)(oh + ki) - 1;
        int iw = (int)(ow + kj) - 1;

        float val = 0.0f;
        if ((unsigned)ih < (unsigned)H_ && (unsigned)iw < (unsigned)W_) {
            val = __ldg(x + ((size_t)bc * H_ + (unsigned)ih) * W_ + (unsigned)iw);
        }
        vp[t] = val;
    }

    // Streaming store: don't let the 458MB write stream evict the 51MB input
    // (input fits in L2 -> 9x read reuse served from L2).
    __stcs(reinterpret_cast<float4*>(out) + i4, v);
}

extern "C" void kernel_launch(void* const* d_in, const int* in_sizes, int n_in,
                              void* d_out, int out_size) {
    const float* x = (const float*)d_in[0];
    float* out = (float*)d_out;
    unsigned blocks = (N4 + 255u) / 256u;
    unfold_kernel<<<blocks, 256>>>(x, out);
}

// round 2
// speedup vs baseline: 1.8117x; 1.8117x over previous
#include <cuda_runtime.h>
#include <stdint.h>

// IN:  (4, 64, 224, 224) fp32
// OUT: (4, 576, 223*223) fp32
// out[ck, oh*223 + ow] = x[bc, oh+ki-1, ow+kj-1] (0 out of bounds)
//   where ck = bc*9 + ki*3 + kj
#define H_    224
#define W_    224
#define OH_   223
#define OW_   223
#define OSP   49729u              // 223*223
#define NROWS 513792u             // 2304 * 223
#define WARPS_PER_BLOCK 8u
#define NBLOCKS (NROWS / WARPS_PER_BLOCK)   // 64224 exactly

__global__ void __launch_bounds__(256) unfold_rows(const float* __restrict__ x,
                                                   float* __restrict__ out) {
    unsigned warp = blockIdx.x * WARPS_PER_BLOCK + (threadIdx.x >> 5);
    unsigned lane = threadIdx.x & 31u;

    // Warp-uniform decomposition (once per 223 output elements)
    unsigned ck = warp / OH_;          // 0..2303
    unsigned oh = warp - ck * OH_;     // 0..222
    unsigned kj = ck % 3u;
    unsigned t  = ck / 3u;
    unsigned ki = t % 3u;
    unsigned bc = t / 3u;              // b*C + c, 0..255

    int ih = (int)(oh + ki) - 1;
    bool row_ok = (unsigned)ih < (unsigned)H_;

    const float* __restrict__ src = x + ((size_t)bc * H_ + (unsigned)ih) * W_;
    float* __restrict__ dst = out + (size_t)ck * OSP + (size_t)oh * OW_;
    int shift = (int)kj - 1;

#pragma unroll
    for (int i = 0; i < 7; ++i) {
        unsigned ow = lane + 32u * i;
        if (ow < OW_) {
            int iw = (int)ow + shift;
            float v = 0.0f;
            if (row_ok && (unsigned)iw < (unsigned)W_) {
                v = __ldg(src + iw);
            }
            // streaming store: keep the 51MB input resident in L2 for 9x reuse
            __stcs(dst + ow, v);
        }
    }
}

extern "C" void kernel_launch(void* const* d_in, const int* in_sizes, int n_in,
                              void* d_out, int out_size) {
    const float* x = (const float*)d_in[0];
    float* out = (float*)d_out;
    unfold_rows<<<NBLOCKS, 256>>>(x, out);
}